// round 8
// baseline (speedup 1.0000x reference)
#include <cuda_runtime.h>
#include <math.h>
#include <stdint.h>

#define EPSF 1e-6f
#define NINPUT 64
#define NLAYER 63

// ---------------------------------------------------------------------------
// Persistent scratch (no allocations allowed)
// ---------------------------------------------------------------------------
__device__ __align__(16) float    g_lc[512];     // per-layer F constants (63*8 used)
__device__ __align__(16) uint32_t g_Pf[4096];    // tf32 P in mma-B fragment order

// ---------------------------------------------------------------------------
// helpers
// ---------------------------------------------------------------------------
__device__ __forceinline__ uint32_t tf32_rn(float f) {
    uint32_t u;
    asm("cvt.rna.tf32.f32 %0, %1;" : "=r"(u) : "f"(f));
    return u;
}
__device__ __forceinline__ float ex2(float t) {
    float r; asm("ex2.approx.ftz.f32 %0, %1;" : "=f"(r) : "f"(t)); return r;
}
__device__ __forceinline__ float lg2(float t) {
    float r; asm("lg2.approx.ftz.f32 %0, %1;" : "=f"(r) : "f"(t)); return r;
}
__device__ __forceinline__ float rcpf(float t) {
    float r; asm("rcp.approx.ftz.f32 %0, %1;" : "=f"(r) : "f"(t)); return r;
}
__device__ __forceinline__ void mma_tf32(float* d, uint32_t a0, uint32_t a1, uint32_t a2,
                                         uint32_t a3, uint32_t b0, uint32_t b1) {
    asm("mma.sync.aligned.m16n8k8.row.col.f32.tf32.tf32.f32 "
        "{%0,%1,%2,%3}, {%4,%5,%6,%7}, {%8,%9}, {%0,%1,%2,%3};"
        : "+f"(d[0]), "+f"(d[1]), "+f"(d[2]), "+f"(d[3])
        : "r"(a0), "r"(a1), "r"(a2), "r"(a3), "r"(b0), "r"(b1));
}

// ---------------------------------------------------------------------------
// Setup: u/v-form Sinkhorn.  u = 1/(M v); v = 1/(M^T u); P = u (.) M (.) v.
// ---------------------------------------------------------------------------
__global__ __launch_bounds__(256) void setup_kernel(const float* __restrict__ logits,
                                                    const float* __restrict__ weights,
                                                    const float* __restrict__ biases)
{
    __shared__ __align__(16) float M[64 * 68];
    __shared__ __align__(16) float Mt[64 * 68];
    __shared__ __align__(16) float u[64], v[64];
    const int tid = threadIdx.x;

    for (int i = tid; i < 4096; i += 256) {
        int r = i >> 6, c = i & 63;
        float m = __expf(logits[i]);
        M[r * 68 + c]  = m;
        Mt[c * 68 + r] = m;
    }
    if (tid < 64) v[tid] = 1.0f;
    __syncthreads();

    for (int it = 0; it < 20; ++it) {
        if (tid < 64) {                       // u = 1/(M v)   (row normalize)
            const float4* mr = reinterpret_cast<const float4*>(&M[tid * 68]);
            const float4* vv = reinterpret_cast<const float4*>(v);
            float s = 0.0f;
            #pragma unroll
            for (int q = 0; q < 16; ++q) {
                float4 a = mr[q], b = vv[q];
                s += a.x * b.x + a.y * b.y + a.z * b.z + a.w * b.w;
            }
            u[tid] = rcpf(s);
        }
        __syncthreads();
        if (tid < 64) {                       // v = 1/(M^T u) (col normalize)
            const float4* mr = reinterpret_cast<const float4*>(&Mt[tid * 68]);
            const float4* uu = reinterpret_cast<const float4*>(u);
            float s = 0.0f;
            #pragma unroll
            for (int q = 0; q < 16; ++q) {
                float4 a = mr[q], b = uu[q];
                s += a.x * b.x + a.y * b.y + a.z * b.z + a.w * b.w;
            }
            v[tid] = rcpf(s);
        }
        __syncthreads();
    }

    // Fragment-ordered B: g_Pf[((kt*8+nt)*32 + lane)*2 + j] = tf32(P[kt*8+tg+4j][nt*8+g])
    for (int i = tid; i < 4096; i += 256) {
        int j = i & 1, ln = (i >> 1) & 31, ntk = i >> 6;
        int nt = ntk & 7, kt = ntk >> 3;
        int g = ln >> 2, tg = ln & 3;
        int k = kt * 8 + tg + 4 * j, n = nt * 8 + g;
        g_Pf[i] = tf32_rn(u[k] * M[k * 68 + n] * v[n]);
    }

    // Per-layer constants: r = A + bw0*xc + bw1*yc + C * exp2(e0*log2(xs)+e1*log2(ys))
    if (tid < NLAYER) {
        float w0 = weights[tid], w1 = 1.0f - w0, a = biases[tid];
        float A, C, cl, e0 = 0.0f, e1 = 0.0f, off;
        if (fabsf(a - 0.5f) < EPSF) {
            A = 0.0f; cl = 1.0f; C = 0.0f; off = 0.0f;
        } else if (a < 0.5f) {
            float ar = fminf(fmaxf(1.0f - a, -1.0f + EPSF), 2.0f - EPSF);
            float p  = sqrtf(3.0f / fmaxf(2.0f - ar, EPSF)) - 1.0f;
            e0 = 2.0f * w0 * p; e1 = 2.0f * w1 * p;
            float bl, bg;
            if      (fabsf(ar - 2.0f) < EPSF) { bl = 0.0f; bg = 0.0f; }
            else if (ar >= 0.75f)             { bl = 0.0f; bg = 1.0f; }
            else if (ar > 0.5f)               { bl = 3.0f - 4.0f * ar; bg = 4.0f * ar - 2.0f; }
            else                              { bl = 1.0f; bg = 0.0f; }
            A = 1.0f - bl; cl = bl; C = -bg; off = 1.0f;
        } else {
            float p = sqrtf(3.0f / fmaxf(2.0f - a, EPSF)) - 1.0f;
            e0 = 2.0f * w0 * p; e1 = 2.0f * w1 * p;
            float bl, bg;
            if      (fabsf(a - 2.0f) < EPSF) { bl = 0.0f; bg = 0.0f; }
            else if (a >= 0.75f)             { bl = 0.0f; bg = 1.0f; }
            else if (a > 0.5f)               { bl = 3.0f - 4.0f * a; bg = 4.0f * a - 2.0f; }
            else                             { bl = 1.0f; bg = 0.0f; }
            A = 0.0f; cl = bl; C = bg; off = 0.0f;
        }
        float* lc = &g_lc[tid * 8];
        lc[0] = cl * w0; lc[1] = cl * w1; lc[2] = A;   lc[3] = C;
        lc[4] = e0;      lc[5] = e1;      lc[6] = off; lc[7] = a;
    }
}

// ---------------------------------------------------------------------------
// Main: 128 threads / CTA, 128 rows; each warp owns a PRIVATE 8704-B SMEM
// slice (X: 32 rows x 68 tf32, aliased by SL: 64 leaves x 34 f32). All phases
// warp-local (no __syncthreads). 6 CTAs/SM (reg cap 85, smem 6x34816=209KB).
// ---------------------------------------------------------------------------
#define XS 68
#define LS 34
#define SLICE_W 2176                      // 8704 B per warp, in words
#define SM_SIZE (4 * 8704)                // 34816 B per CTA

__global__ __launch_bounds__(128, 6) void main_kernel(const float* __restrict__ x,
                                                      float* __restrict__ out,
                                                      int batch)
{
    extern __shared__ __align__(16) uint8_t smem[];
    const int tid = threadIdx.x, w = tid >> 5, lane = tid & 31;
    const int g = lane >> 2, tg = lane & 3;

    uint32_t* sXw  = reinterpret_cast<uint32_t*>(smem) + w * SLICE_W;
    float*    sSLw = reinterpret_cast<float*>(smem) + w * SLICE_W;

    // ---- stage this warp's 32 rows: 512 float4, coalesced ----
    const size_t f4_limit = (size_t)batch * 16;
    const size_t f4_base  = (size_t)blockIdx.x * 2048 + (size_t)w * 512;
    const float4* gx = reinterpret_cast<const float4*>(x);
    #pragma unroll
    for (int t = 0; t < 16; ++t) {
        int i = lane + t * 32;
        size_t gi = f4_base + i;
        float4 v = (gi < f4_limit) ? __ldcs(&gx[gi]) : make_float4(0.f, 0.f, 0.f, 0.f);
        uint4 uv;
        uv.x = tf32_rn(v.x); uv.y = tf32_rn(v.y); uv.z = tf32_rn(v.z); uv.w = tf32_rn(v.w);
        int r = i >> 4, c = (i & 15) << 2;
        *reinterpret_cast<uint4*>(&sXw[r * XS + c]) = uv;
    }
    __syncwarp();

    // ---- GEMM: this warp's 32 rows x 64 leaves (2 m-tiles) ----
    float d[2][8][4];
    #pragma unroll
    for (int mt = 0; mt < 2; ++mt)
        #pragma unroll
        for (int nt = 0; nt < 8; ++nt)
            #pragma unroll
            for (int e = 0; e < 4; ++e) d[mt][nt][e] = 0.0f;

    const uint2* Pf2 = reinterpret_cast<const uint2*>(g_Pf);
    #pragma unroll
    for (int kt = 0; kt < 8; ++kt) {
        const int c0 = kt * 8 + tg;
        uint32_t a[2][4];
        #pragma unroll
        for (int mt = 0; mt < 2; ++mt) {
            int r0 = g + mt * 16;                      // local rows g+16mt, +8
            a[mt][0] = sXw[r0 * XS + c0];
            a[mt][1] = sXw[(r0 + 8) * XS + c0];
            a[mt][2] = sXw[r0 * XS + c0 + 4];
            a[mt][3] = sXw[(r0 + 8) * XS + c0 + 4];
        }
        #pragma unroll
        for (int nt = 0; nt < 8; ++nt) {
            uint2 b = __ldg(&Pf2[(kt * 8 + nt) * 32 + lane]);
            mma_tf32(d[0][nt], a[0][0], a[0][1], a[0][2], a[0][3], b.x, b.y);
            mma_tf32(d[1][nt], a[1][0], a[1][1], a[1][2], a[1][3], b.x, b.y);
        }
    }
    __syncwarp();      // warp done reading X slice before SL aliases it

    // ---- epilogue: D -> SL[leaf][local row] (stride 34, conflict-free) ----
    #pragma unroll
    for (int mt = 0; mt < 2; ++mt) {
        int r0 = mt * 16 + g;
        #pragma unroll
        for (int nt = 0; nt < 8; ++nt) {
            int c0 = nt * 8 + tg * 2;
            sSLw[c0 * LS + r0]           = d[mt][nt][0];
            sSLw[(c0 + 1) * LS + r0]     = d[mt][nt][1];
            sSLw[c0 * LS + r0 + 8]       = d[mt][nt][2];
            sSLw[(c0 + 1) * LS + r0 + 8] = d[mt][nt][3];
        }
    }
    __syncwarp();

    // ---- 63-layer scan: thread scans its local row (= lane) ----
    // Layer consts via uniform __ldg (L1 broadcast, off the serial chain).
    // NaN fallback dropped: e0,e1 >= 0 and xs,ys >= EPSF => result always finite.
    const float4* lc4 = reinterpret_cast<const float4*>(g_lc);
    float state = sSLw[lane];
    #pragma unroll
    for (int i = 0; i < NLAYER; ++i) {
        float leaf = sSLw[(i + 1) * LS + lane];
        float4 k0 = __ldg(&lc4[i * 2]);
        float4 k1 = __ldg(&lc4[i * 2 + 1]);

        float xc = fminf(fmaxf(state, EPSF), 1.0f - EPSF);
        float yc = fminf(fmaxf(leaf,  EPSF), 1.0f - EPSF);
        float lgx = lg2(fabsf(k1.z - xc));
        float lgy = lg2(fabsf(k1.z - yc));
        float t  = fmaf(k1.x, lgx, k1.y * lgy);
        float gg = ex2(t);
        state = fmaf(k0.w, gg, fmaf(k0.y, yc, fmaf(k0.x, xc, k0.z)));
    }

    int row = blockIdx.x * 128 + w * 32 + lane;
    if (row < batch) out[row] = state;
}

// ---------------------------------------------------------------------------
// Launch
// ---------------------------------------------------------------------------
extern "C" void kernel_launch(void* const* d_in, const int* in_sizes, int n_in,
                              void* d_out, int out_size)
{
    const float* x       = (const float*)d_in[0];
    const float* logits  = (const float*)d_in[1];
    const float* weights = (const float*)d_in[2];
    const float* biases  = (const float*)d_in[3];
    float* out = (float*)d_out;

    int batch = in_sizes[0] / NINPUT;

    cudaFuncSetAttribute(main_kernel, cudaFuncAttributeMaxDynamicSharedMemorySize, SM_SIZE);

    setup_kernel<<<1, 256>>>(logits, weights, biases);
    main_kernel<<<(batch + 127) / 128, 128, SM_SIZE>>>(x, out, batch);
}

// round 9
// speedup vs baseline: 1.5367x; 1.5367x over previous
#include <cuda_runtime.h>
#include <cuda_fp16.h>
#include <math.h>
#include <stdint.h>

#define EPSF 1e-6f
#define NINPUT 64
#define NLAYER 63

// ---------------------------------------------------------------------------
// Persistent scratch (no allocations allowed)
// ---------------------------------------------------------------------------
__device__ __align__(16) float g_lc[512];     // per-layer F constants (63*8 used)
__device__ __align__(16) uint2 g_Pf[1024];    // fp16 P in m16n8k16 B-fragment order

// ---------------------------------------------------------------------------
// helpers
// ---------------------------------------------------------------------------
__device__ __forceinline__ float ex2(float t) {
    float r; asm("ex2.approx.ftz.f32 %0, %1;" : "=f"(r) : "f"(t)); return r;
}
__device__ __forceinline__ float lg2(float t) {
    float r; asm("lg2.approx.ftz.f32 %0, %1;" : "=f"(r) : "f"(t)); return r;
}
__device__ __forceinline__ float rcpf(float t) {
    float r; asm("rcp.approx.ftz.f32 %0, %1;" : "=f"(r) : "f"(t)); return r;
}
__device__ __forceinline__ uint32_t f16x2_rn(float lo, float hi) {
    __half2 h = __floats2half2_rn(lo, hi);           // .x = lo, .y = hi
    return *reinterpret_cast<uint32_t*>(&h);
}
__device__ __forceinline__ void mma_fp16(float* d, const uint32_t* a, uint32_t b0,
                                         uint32_t b1) {
    asm("mma.sync.aligned.m16n8k16.row.col.f32.f16.f16.f32 "
        "{%0,%1,%2,%3}, {%4,%5,%6,%7}, {%8,%9}, {%0,%1,%2,%3};"
        : "+f"(d[0]), "+f"(d[1]), "+f"(d[2]), "+f"(d[3])
        : "r"(a[0]), "r"(a[1]), "r"(a[2]), "r"(a[3]), "r"(b0), "r"(b1));
}

// ---------------------------------------------------------------------------
// Setup: u/v-form Sinkhorn (4-way ILP dots) -> fp16 fragment-ordered P + consts
// ---------------------------------------------------------------------------
__global__ __launch_bounds__(256) void setup_kernel(const float* __restrict__ logits,
                                                    const float* __restrict__ weights,
                                                    const float* __restrict__ biases)
{
    __shared__ __align__(16) float M[64 * 68];
    __shared__ __align__(16) float Mt[64 * 68];
    __shared__ __align__(16) float u[64], v[64];
    const int tid = threadIdx.x;

    for (int i = tid; i < 4096; i += 256) {
        int r = i >> 6, c = i & 63;
        float m = __expf(logits[i]);
        M[r * 68 + c]  = m;
        Mt[c * 68 + r] = m;
    }
    if (tid < 64) v[tid] = 1.0f;
    __syncthreads();

    for (int it = 0; it < 20; ++it) {
        if (tid < 64) {                       // u = 1/(M v)
            const float4* mr = reinterpret_cast<const float4*>(&M[tid * 68]);
            const float4* vv = reinterpret_cast<const float4*>(v);
            float s0 = 0.f, s1 = 0.f, s2 = 0.f, s3 = 0.f;
            #pragma unroll
            for (int q = 0; q < 16; ++q) {
                float4 a = mr[q], b = vv[q];
                s0 = fmaf(a.x, b.x, s0); s1 = fmaf(a.y, b.y, s1);
                s2 = fmaf(a.z, b.z, s2); s3 = fmaf(a.w, b.w, s3);
            }
            u[tid] = rcpf((s0 + s1) + (s2 + s3));
        }
        __syncthreads();
        if (tid < 64) {                       // v = 1/(M^T u)
            const float4* mr = reinterpret_cast<const float4*>(&Mt[tid * 68]);
            const float4* uu = reinterpret_cast<const float4*>(u);
            float s0 = 0.f, s1 = 0.f, s2 = 0.f, s3 = 0.f;
            #pragma unroll
            for (int q = 0; q < 16; ++q) {
                float4 a = mr[q], b = uu[q];
                s0 = fmaf(a.x, b.x, s0); s1 = fmaf(a.y, b.y, s1);
                s2 = fmaf(a.z, b.z, s2); s3 = fmaf(a.w, b.w, s3);
            }
            v[tid] = rcpf((s0 + s1) + (s2 + s3));
        }
        __syncthreads();
    }

    // m16n8k16 B-fragment order:
    //   g_Pf[(kt*8+nt)*32 + lane] = { f16x2(P[16kt+2tg][8nt+g], P[16kt+2tg+1][8nt+g]),
    //                                 f16x2(P[16kt+2tg+8][8nt+g], P[16kt+2tg+9][8nt+g]) }
    for (int i = tid; i < 1024; i += 256) {
        int lane = i & 31, ntk = i >> 5;
        int nt = ntk & 7, kt = ntk >> 3;
        int g = lane >> 2, tg = lane & 3;
        int k0 = kt * 16 + 2 * tg, n = nt * 8 + g;
        float p0 = u[k0]     * M[k0 * 68 + n]       * v[n];
        float p1 = u[k0 + 1] * M[(k0 + 1) * 68 + n] * v[n];
        float p8 = u[k0 + 8] * M[(k0 + 8) * 68 + n] * v[n];
        float p9 = u[k0 + 9] * M[(k0 + 9) * 68 + n] * v[n];
        g_Pf[i] = make_uint2(f16x2_rn(p0, p1), f16x2_rn(p8, p9));
    }

    // Per-layer constants: r = A + bw0*xc + bw1*yc + C * exp2(e0*log2(xs)+e1*log2(ys))
    if (tid < NLAYER) {
        float w0 = weights[tid], w1 = 1.0f - w0, a = biases[tid];
        float A, C, cl, e0 = 0.0f, e1 = 0.0f, off;
        if (fabsf(a - 0.5f) < EPSF) {
            A = 0.0f; cl = 1.0f; C = 0.0f; off = 0.0f;
        } else if (a < 0.5f) {
            float ar = fminf(fmaxf(1.0f - a, -1.0f + EPSF), 2.0f - EPSF);
            float p  = sqrtf(3.0f / fmaxf(2.0f - ar, EPSF)) - 1.0f;
            e0 = 2.0f * w0 * p; e1 = 2.0f * w1 * p;
            float bl, bg;
            if      (fabsf(ar - 2.0f) < EPSF) { bl = 0.0f; bg = 0.0f; }
            else if (ar >= 0.75f)             { bl = 0.0f; bg = 1.0f; }
            else if (ar > 0.5f)               { bl = 3.0f - 4.0f * ar; bg = 4.0f * ar - 2.0f; }
            else                              { bl = 1.0f; bg = 0.0f; }
            A = 1.0f - bl; cl = bl; C = -bg; off = 1.0f;
        } else {
            float p = sqrtf(3.0f / fmaxf(2.0f - a, EPSF)) - 1.0f;
            e0 = 2.0f * w0 * p; e1 = 2.0f * w1 * p;
            float bl, bg;
            if      (fabsf(a - 2.0f) < EPSF) { bl = 0.0f; bg = 0.0f; }
            else if (a >= 0.75f)             { bl = 0.0f; bg = 1.0f; }
            else if (a > 0.5f)               { bl = 3.0f - 4.0f * a; bg = 4.0f * a - 2.0f; }
            else                             { bl = 1.0f; bg = 0.0f; }
            A = 0.0f; cl = bl; C = bg; off = 0.0f;
        }
        float* lc = &g_lc[tid * 8];
        lc[0] = cl * w0; lc[1] = cl * w1; lc[2] = A;   lc[3] = C;
        lc[4] = e0;      lc[5] = e1;      lc[6] = off; lc[7] = a;
    }
}

// ---------------------------------------------------------------------------
// Main: 128 threads / CTA, 128 rows; warp-private 8704-B SMEM slice.
//   X: fp16 [32 r][36 word-cols] (word = 2 fp16 cols; A-frag bank = 4g+tg = lane)
//   SL (aliases X after GEMM): f32 [64 leaf][34] (epilogue 4tg+g inj; scan coalesced)
// fp16 m16n8k16 MMA: 64 MMAs/warp (half of tf32 path), identical 10-bit precision.
// No __syncthreads anywhere; 5 CTAs/SM.
// ---------------------------------------------------------------------------
#define XS2 36
#define LS 34
#define SLICE_W 2176                      // 8704 B per warp, in words
#define SM_SIZE (4 * 8704)                // 34816 B per CTA

__global__ __launch_bounds__(128, 5) void main_kernel(const float* __restrict__ x,
                                                      float* __restrict__ out,
                                                      int batch)
{
    extern __shared__ __align__(16) uint8_t smem[];
    const int tid = threadIdx.x, w = tid >> 5, lane = tid & 31;
    const int g = lane >> 2, tg = lane & 3;

    uint32_t* sXw  = reinterpret_cast<uint32_t*>(smem) + w * SLICE_W;
    float*    sSLw = reinterpret_cast<float*>(smem) + w * SLICE_W;

    // ---- stage this warp's 32 rows: 512 float4 -> fp16 pairs ----
    const size_t f4_limit = (size_t)batch * 16;
    const size_t f4_base  = (size_t)blockIdx.x * 2048 + (size_t)w * 512;
    const float4* gx = reinterpret_cast<const float4*>(x);
    #pragma unroll
    for (int t = 0; t < 16; ++t) {
        int i = lane + t * 32;
        size_t gi = f4_base + i;
        float4 v = (gi < f4_limit) ? __ldcs(&gx[gi]) : make_float4(0.f, 0.f, 0.f, 0.f);
        uint2 hv = make_uint2(f16x2_rn(v.x, v.y), f16x2_rn(v.z, v.w));
        int r = i >> 4, wc = (i & 15) << 1;
        *reinterpret_cast<uint2*>(&sXw[r * XS2 + wc]) = hv;
    }
    __syncwarp();

    // ---- GEMM: this warp's 32 rows x 64 leaves, fp16 k16 (4 kt steps) ----
    float d[2][8][4];
    #pragma unroll
    for (int mt = 0; mt < 2; ++mt)
        #pragma unroll
        for (int nt = 0; nt < 8; ++nt)
            #pragma unroll
            for (int e = 0; e < 4; ++e) d[mt][nt][e] = 0.0f;

    #pragma unroll
    for (int kt = 0; kt < 4; ++kt) {
        const int wc0 = kt * 8 + tg;
        uint32_t a[2][4];
        #pragma unroll
        for (int mt = 0; mt < 2; ++mt) {
            int r0 = g + mt * 16;
            a[mt][0] = sXw[r0 * XS2 + wc0];
            a[mt][1] = sXw[(r0 + 8) * XS2 + wc0];
            a[mt][2] = sXw[r0 * XS2 + wc0 + 4];
            a[mt][3] = sXw[(r0 + 8) * XS2 + wc0 + 4];
        }
        #pragma unroll
        for (int nt = 0; nt < 8; ++nt) {
            uint2 b = __ldg(&g_Pf[(kt * 8 + nt) * 32 + lane]);
            mma_fp16(d[0][nt], a[0], b.x, b.y);
            mma_fp16(d[1][nt], a[1], b.x, b.y);
        }
    }
    __syncwarp();      // warp done reading X slice before SL aliases it

    // ---- epilogue: D -> SL[leaf][local row] (stride 34, conflict-free) ----
    #pragma unroll
    for (int mt = 0; mt < 2; ++mt) {
        int r0 = mt * 16 + g;
        #pragma unroll
        for (int nt = 0; nt < 8; ++nt) {
            int c0 = nt * 8 + tg * 2;
            sSLw[c0 * LS + r0]           = d[mt][nt][0];
            sSLw[(c0 + 1) * LS + r0]     = d[mt][nt][1];
            sSLw[c0 * LS + r0 + 8]       = d[mt][nt][2];
            sSLw[(c0 + 1) * LS + r0 + 8] = d[mt][nt][3];
        }
    }
    __syncwarp();

    // ---- 63-layer scan: thread scans its local row (= lane) ----
    // NaN fallback dropped: e0,e1 >= 0 and xs,ys >= EPSF => result always finite.
    const float4* lc4 = reinterpret_cast<const float4*>(g_lc);
    float state = sSLw[lane];
    #pragma unroll
    for (int i = 0; i < NLAYER; ++i) {
        float leaf = sSLw[(i + 1) * LS + lane];
        float4 k0 = __ldg(&lc4[i * 2]);
        float4 k1 = __ldg(&lc4[i * 2 + 1]);

        float xc = fminf(fmaxf(state, EPSF), 1.0f - EPSF);
        float yc = fminf(fmaxf(leaf,  EPSF), 1.0f - EPSF);
        float lgx = lg2(fabsf(k1.z - xc));
        float lgy = lg2(fabsf(k1.z - yc));
        float t  = fmaf(k1.x, lgx, k1.y * lgy);
        float gg = ex2(t);
        state = fmaf(k0.w, gg, fmaf(k0.y, yc, fmaf(k0.x, xc, k0.z)));
    }

    int row = blockIdx.x * 128 + w * 32 + lane;
    if (row < batch) out[row] = state;
}

// ---------------------------------------------------------------------------
// Launch
// ---------------------------------------------------------------------------
extern "C" void kernel_launch(void* const* d_in, const int* in_sizes, int n_in,
                              void* d_out, int out_size)
{
    const float* x       = (const float*)d_in[0];
    const float* logits  = (const float*)d_in[1];
    const float* weights = (const float*)d_in[2];
    const float* biases  = (const float*)d_in[3];
    float* out = (float*)d_out;

    int batch = in_sizes[0] / NINPUT;

    cudaFuncSetAttribute(main_kernel, cudaFuncAttributeMaxDynamicSharedMemorySize, SM_SIZE);

    setup_kernel<<<1, 256>>>(logits, weights, biases);
    main_kernel<<<(batch + 127) / 128, 128, SM_SIZE>>>(x, out, batch);
}

// round 10
// speedup vs baseline: 1.6169x; 1.0522x over previous
#include <cuda_runtime.h>
#include <cuda_fp16.h>
#include <math.h>
#include <stdint.h>

#define EPSF 1e-6f
#define NINPUT 64
#define NLAYER 63

// ---------------------------------------------------------------------------
// Persistent scratch (no allocations allowed)
// ---------------------------------------------------------------------------
__device__ __align__(16) float g_lc[512];     // per-layer F constants (63*8 used)
__device__ __align__(16) uint2 g_Pf[1024];    // fp16 P in m16n8k16 B-fragment order

// ---------------------------------------------------------------------------
// helpers
// ---------------------------------------------------------------------------
__device__ __forceinline__ float ex2(float t) {
    float r; asm("ex2.approx.ftz.f32 %0, %1;" : "=f"(r) : "f"(t)); return r;
}
__device__ __forceinline__ float lg2(float t) {
    float r; asm("lg2.approx.ftz.f32 %0, %1;" : "=f"(r) : "f"(t)); return r;
}
__device__ __forceinline__ float rcpf(float t) {
    float r; asm("rcp.approx.ftz.f32 %0, %1;" : "=f"(r) : "f"(t)); return r;
}
__device__ __forceinline__ uint32_t f16x2_rn(float lo, float hi) {
    __half2 h = __floats2half2_rn(lo, hi);
    return *reinterpret_cast<uint32_t*>(&h);
}
__device__ __forceinline__ uint32_t ldpack(const float* p) {   // 2 f32 -> f16x2
    float2 f = *reinterpret_cast<const float2*>(p);
    return f16x2_rn(f.x, f.y);
}
__device__ __forceinline__ void mma_fp16(float* d, const uint32_t* a, uint32_t b0,
                                         uint32_t b1) {
    asm("mma.sync.aligned.m16n8k16.row.col.f32.f16.f16.f32 "
        "{%0,%1,%2,%3}, {%4,%5,%6,%7}, {%8,%9}, {%0,%1,%2,%3};"
        : "+f"(d[0]), "+f"(d[1]), "+f"(d[2]), "+f"(d[3])
        : "r"(a[0]), "r"(a[1]), "r"(a[2]), "r"(a[3]), "r"(b0), "r"(b1));
}

// ---------------------------------------------------------------------------
// Setup: u/v-form Sinkhorn (4-way ILP dots) -> fp16 fragment-ordered P + consts
// ---------------------------------------------------------------------------
__global__ __launch_bounds__(256) void setup_kernel(const float* __restrict__ logits,
                                                    const float* __restrict__ weights,
                                                    const float* __restrict__ biases)
{
    __shared__ __align__(16) float M[64 * 68];
    __shared__ __align__(16) float Mt[64 * 68];
    __shared__ __align__(16) float u[64], v[64];
    const int tid = threadIdx.x;

    for (int i = tid; i < 4096; i += 256) {
        int r = i >> 6, c = i & 63;
        float m = __expf(logits[i]);
        M[r * 68 + c]  = m;
        Mt[c * 68 + r] = m;
    }
    if (tid < 64) v[tid] = 1.0f;
    __syncthreads();

    for (int it = 0; it < 20; ++it) {
        if (tid < 64) {                       // u = 1/(M v)
            const float4* mr = reinterpret_cast<const float4*>(&M[tid * 68]);
            const float4* vv = reinterpret_cast<const float4*>(v);
            float s0 = 0.f, s1 = 0.f, s2 = 0.f, s3 = 0.f;
            #pragma unroll
            for (int q = 0; q < 16; ++q) {
                float4 a = mr[q], b = vv[q];
                s0 = fmaf(a.x, b.x, s0); s1 = fmaf(a.y, b.y, s1);
                s2 = fmaf(a.z, b.z, s2); s3 = fmaf(a.w, b.w, s3);
            }
            u[tid] = rcpf((s0 + s1) + (s2 + s3));
        }
        __syncthreads();
        if (tid < 64) {                       // v = 1/(M^T u)
            const float4* mr = reinterpret_cast<const float4*>(&Mt[tid * 68]);
            const float4* uu = reinterpret_cast<const float4*>(u);
            float s0 = 0.f, s1 = 0.f, s2 = 0.f, s3 = 0.f;
            #pragma unroll
            for (int q = 0; q < 16; ++q) {
                float4 a = mr[q], b = uu[q];
                s0 = fmaf(a.x, b.x, s0); s1 = fmaf(a.y, b.y, s1);
                s2 = fmaf(a.z, b.z, s2); s3 = fmaf(a.w, b.w, s3);
            }
            v[tid] = rcpf((s0 + s1) + (s2 + s3));
        }
        __syncthreads();
    }

    // m16n8k16 B-fragment order (R9-verified):
    //   g_Pf[(kt*8+nt)*32 + lane] = { f16x2(P[16kt+2tg][8nt+g], P[16kt+2tg+1][8nt+g]),
    //                                 f16x2(P[16kt+2tg+8][8nt+g], P[16kt+2tg+9][8nt+g]) }
    for (int i = tid; i < 1024; i += 256) {
        int lane = i & 31, ntk = i >> 5;
        int nt = ntk & 7, kt = ntk >> 3;
        int g = lane >> 2, tg = lane & 3;
        int k0 = kt * 16 + 2 * tg, n = nt * 8 + g;
        float p0 = u[k0]     * M[k0 * 68 + n]       * v[n];
        float p1 = u[k0 + 1] * M[(k0 + 1) * 68 + n] * v[n];
        float p8 = u[k0 + 8] * M[(k0 + 8) * 68 + n] * v[n];
        float p9 = u[k0 + 9] * M[(k0 + 9) * 68 + n] * v[n];
        g_Pf[i] = make_uint2(f16x2_rn(p0, p1), f16x2_rn(p8, p9));
    }

    // Per-layer constants: r = A + bw0*xc + bw1*yc + C * exp2(e0*log2(xs)+e1*log2(ys))
    if (tid < NLAYER) {
        float w0 = weights[tid], w1 = 1.0f - w0, a = biases[tid];
        float A, C, cl, e0 = 0.0f, e1 = 0.0f, off;
        if (fabsf(a - 0.5f) < EPSF) {
            A = 0.0f; cl = 1.0f; C = 0.0f; off = 0.0f;
        } else if (a < 0.5f) {
            float ar = fminf(fmaxf(1.0f - a, -1.0f + EPSF), 2.0f - EPSF);
            float p  = sqrtf(3.0f / fmaxf(2.0f - ar, EPSF)) - 1.0f;
            e0 = 2.0f * w0 * p; e1 = 2.0f * w1 * p;
            float bl, bg;
            if      (fabsf(ar - 2.0f) < EPSF) { bl = 0.0f; bg = 0.0f; }
            else if (ar >= 0.75f)             { bl = 0.0f; bg = 1.0f; }
            else if (ar > 0.5f)               { bl = 3.0f - 4.0f * ar; bg = 4.0f * ar - 2.0f; }
            else                              { bl = 1.0f; bg = 0.0f; }
            A = 1.0f - bl; cl = bl; C = -bg; off = 1.0f;
        } else {
            float p = sqrtf(3.0f / fmaxf(2.0f - a, EPSF)) - 1.0f;
            e0 = 2.0f * w0 * p; e1 = 2.0f * w1 * p;
            float bl, bg;
            if      (fabsf(a - 2.0f) < EPSF) { bl = 0.0f; bg = 0.0f; }
            else if (a >= 0.75f)             { bl = 0.0f; bg = 1.0f; }
            else if (a > 0.5f)               { bl = 3.0f - 4.0f * a; bg = 4.0f * a - 2.0f; }
            else                             { bl = 1.0f; bg = 0.0f; }
            A = 0.0f; cl = bl; C = bg; off = 0.0f;
        }
        float* lc = &g_lc[tid * 8];
        lc[0] = cl * w0; lc[1] = cl * w1; lc[2] = A;   lc[3] = C;
        lc[4] = e0;      lc[5] = e1;      lc[6] = off; lc[7] = a;
    }
}

// ---------------------------------------------------------------------------
// Main: PERSISTENT warps + cp.async double buffering. 444 CTAs x 128 thr.
// Each warp grid-strides over 32-row tiles; two private f32 X buffers
// (32 r x 72 words; A-frag LDS.64 bank pair = 4g+tg, injective). While tile i
// is computed, tile i+1 streams into the other buffer via cp.async.cg
// (L1-bypass, no register staging). SL (64 x 34 f32) aliases the consumed
// buffer. fp16 m16n8k16 MMA; conversion f32->f16x2 at fragment load.
// ---------------------------------------------------------------------------
#define XW 72
#define XBUF_W 2304                       // 32*72 words = 9216 B
#define LS 34
#define WSLICE_W (2 * XBUF_W)             // per-warp words
#define SM_SIZE (4 * 2 * 9216)            // 73728 B per CTA -> 3 CTAs/SM
#define NCTAS 444

__global__ __launch_bounds__(128, 3) void main_kernel(const float* __restrict__ x,
                                                      float* __restrict__ out,
                                                      int batch)
{
    extern __shared__ __align__(16) uint8_t smem[];
    const int tid = threadIdx.x, w = tid >> 5, lane = tid & 31;
    const int g = lane >> 2, tg = lane & 3;

    float* Wbase = reinterpret_cast<float*>(smem) + w * WSLICE_W;
    uint32_t sbase;
    asm("{ .reg .u64 t; cvta.to.shared.u64 t, %1; cvt.u32.u64 %0, t; }"
        : "=r"(sbase) : "l"(Wbase));

    const int ntiles = (batch + 31) >> 5;
    const int warpId = blockIdx.x * 4 + w;
    const int wstride = gridDim.x * 4;
    const size_t f4_limit = (size_t)batch * 16;
    const float4* gx = reinterpret_cast<const float4*>(x);

    // issue one 32-row tile into buffer p (16 x 16B cp.async per thread)
    auto issue = [&](int tile, int p) {
        if (tile < ntiles) {
            uint32_t dstb = sbase + p * 9216;
            #pragma unroll
            for (int t = 0; t < 16; ++t) {
                int i = lane + t * 32;
                size_t gi = (size_t)tile * 512 + i;
                if (gi < f4_limit) {
                    int r = i >> 4, c4 = i & 15;
                    uint32_t d = dstb + (uint32_t)(r * XW + c4 * 4) * 4;
                    asm volatile("cp.async.cg.shared.global [%0], [%1], 16;"
                                 :: "r"(d), "l"(gx + gi) : "memory");
                }
            }
        }
        asm volatile("cp.async.commit_group;" ::: "memory");
    };

    issue(warpId, 0);
    issue(warpId + wstride, 1);

    int p = 0;
    for (int tile = warpId; tile < ntiles; tile += wstride) {
        asm volatile("cp.async.wait_group 1;" ::: "memory");
        __syncwarp();

        const float* Xb = Wbase + p * XBUF_W;

        // ---- GEMM: 32 rows x 64 leaves, fp16 m16n8k16, 4 k-steps ----
        float d[2][8][4];
        #pragma unroll
        for (int mt = 0; mt < 2; ++mt)
            #pragma unroll
            for (int nt = 0; nt < 8; ++nt)
                #pragma unroll
                for (int e = 0; e < 4; ++e) d[mt][nt][e] = 0.0f;

        #pragma unroll
        for (int kt = 0; kt < 4; ++kt) {
            const int kc = kt * 16 + 2 * tg;
            uint32_t a[2][4];
            #pragma unroll
            for (int mt = 0; mt < 2; ++mt) {
                int r0 = g + mt * 16;
                a[mt][0] = ldpack(&Xb[r0 * XW + kc]);
                a[mt][1] = ldpack(&Xb[(r0 + 8) * XW + kc]);
                a[mt][2] = ldpack(&Xb[r0 * XW + kc + 8]);
                a[mt][3] = ldpack(&Xb[(r0 + 8) * XW + kc + 8]);
            }
            #pragma unroll
            for (int nt = 0; nt < 8; ++nt) {
                uint2 b = __ldg(&g_Pf[(kt * 8 + nt) * 32 + lane]);
                mma_fp16(d[0][nt], a[0], b.x, b.y);
                mma_fp16(d[1][nt], a[1], b.x, b.y);
            }
        }
        __syncwarp();            // done reading Xb; SL may alias it

        // ---- epilogue: D -> SL[leaf][local row] ----
        float* SLb = Wbase + p * XBUF_W;
        #pragma unroll
        for (int mt = 0; mt < 2; ++mt) {
            int r0 = mt * 16 + g;
            #pragma unroll
            for (int nt = 0; nt < 8; ++nt) {
                int c0 = nt * 8 + tg * 2;
                SLb[c0 * LS + r0]           = d[mt][nt][0];
                SLb[(c0 + 1) * LS + r0]     = d[mt][nt][1];
                SLb[c0 * LS + r0 + 8]       = d[mt][nt][2];
                SLb[(c0 + 1) * LS + r0 + 8] = d[mt][nt][3];
            }
        }
        __syncwarp();

        // ---- 63-layer scan: thread scans its local row (= lane) ----
        const float4* lc4 = reinterpret_cast<const float4*>(g_lc);
        float state = SLb[lane];
        #pragma unroll
        for (int i = 0; i < NLAYER; ++i) {
            float leaf = SLb[(i + 1) * LS + lane];
            float4 k0 = __ldg(&lc4[i * 2]);
            float4 k1 = __ldg(&lc4[i * 2 + 1]);

            float xc = fminf(fmaxf(state, EPSF), 1.0f - EPSF);
            float yc = fminf(fmaxf(leaf,  EPSF), 1.0f - EPSF);
            float lgx = lg2(fabsf(k1.z - xc));
            float lgy = lg2(fabsf(k1.z - yc));
            float t  = fmaf(k1.x, lgx, k1.y * lgy);
            float gg = ex2(t);
            state = fmaf(k0.w, gg, fmaf(k0.y, yc, fmaf(k0.x, xc, k0.z)));
        }

        int row = tile * 32 + lane;
        if (row < batch) out[row] = state;

        __syncwarp();            // all lanes done reading SLb before refill
        issue(tile + 2 * wstride, p);
        p ^= 1;
    }
}

// ---------------------------------------------------------------------------
// Launch
// ---------------------------------------------------------------------------
extern "C" void kernel_launch(void* const* d_in, const int* in_sizes, int n_in,
                              void* d_out, int out_size)
{
    const float* x       = (const float*)d_in[0];
    const float* logits  = (const float*)d_in[1];
    const float* weights = (const float*)d_in[2];
    const float* biases  = (const float*)d_in[3];
    float* out = (float*)d_out;

    int batch = in_sizes[0] / NINPUT;

    cudaFuncSetAttribute(main_kernel, cudaFuncAttributeMaxDynamicSharedMemorySize, SM_SIZE);

    setup_kernel<<<1, 256>>>(logits, weights, biases);
    main_kernel<<<NCTAS, 128, SM_SIZE>>>(x, out, batch);
}

// round 11
// speedup vs baseline: 1.6981x; 1.0502x over previous
#include <cuda_runtime.h>
#include <cuda_fp16.h>
#include <math.h>
#include <stdint.h>

#define EPSF 1e-6f
#define NINPUT 64
#define NLAYER 63

// ---------------------------------------------------------------------------
// Persistent scratch (no allocations allowed)
// ---------------------------------------------------------------------------
__device__ __align__(16) float g_lc[512];     // per-layer F constants (63*8 used)
__device__ __align__(16) uint2 g_Pf[1024];    // fp16 P in m16n8k16 B-fragment order

// Layer constants in the constant bank: folded into FFMA/FMNMX as c-bank
// operands by ptxas -> zero LSU traffic in the scan.
__constant__ float4 c_lc[NLAYER * 2];

// ---------------------------------------------------------------------------
// helpers
// ---------------------------------------------------------------------------
__device__ __forceinline__ float ex2(float t) {
    float r; asm("ex2.approx.ftz.f32 %0, %1;" : "=f"(r) : "f"(t)); return r;
}
__device__ __forceinline__ float lg2(float t) {
    float r; asm("lg2.approx.ftz.f32 %0, %1;" : "=f"(r) : "f"(t)); return r;
}
__device__ __forceinline__ float rcpf(float t) {
    float r; asm("rcp.approx.ftz.f32 %0, %1;" : "=f"(r) : "f"(t)); return r;
}
__device__ __forceinline__ uint32_t f16x2_rn(float lo, float hi) {
    __half2 h = __floats2half2_rn(lo, hi);
    return *reinterpret_cast<uint32_t*>(&h);
}
__device__ __forceinline__ uint32_t ldpack(const float* p) {   // 2 f32 -> f16x2
    float2 f = *reinterpret_cast<const float2*>(p);
    return f16x2_rn(f.x, f.y);
}
__device__ __forceinline__ void mma_fp16(float* d, const uint32_t* a, uint32_t b0,
                                         uint32_t b1) {
    asm("mma.sync.aligned.m16n8k16.row.col.f32.f16.f16.f32 "
        "{%0,%1,%2,%3}, {%4,%5,%6,%7}, {%8,%9}, {%0,%1,%2,%3};"
        : "+f"(d[0]), "+f"(d[1]), "+f"(d[2]), "+f"(d[3])
        : "r"(a[0]), "r"(a[1]), "r"(a[2]), "r"(a[3]), "r"(b0), "r"(b1));
}

// ---------------------------------------------------------------------------
// Setup: u/v-form Sinkhorn (4-way ILP dots) -> fp16 fragment-ordered P + consts
// ---------------------------------------------------------------------------
__global__ __launch_bounds__(256) void setup_kernel(const float* __restrict__ logits,
                                                    const float* __restrict__ weights,
                                                    const float* __restrict__ biases)
{
    __shared__ __align__(16) float M[64 * 68];
    __shared__ __align__(16) float Mt[64 * 68];
    __shared__ __align__(16) float u[64], v[64];
    const int tid = threadIdx.x;

    for (int i = tid; i < 4096; i += 256) {
        int r = i >> 6, c = i & 63;
        float m = __expf(logits[i]);
        M[r * 68 + c]  = m;
        Mt[c * 68 + r] = m;
    }
    if (tid < 64) v[tid] = 1.0f;
    __syncthreads();

    for (int it = 0; it < 20; ++it) {
        if (tid < 64) {                       // u = 1/(M v)
            const float4* mr = reinterpret_cast<const float4*>(&M[tid * 68]);
            const float4* vv = reinterpret_cast<const float4*>(v);
            float s0 = 0.f, s1 = 0.f, s2 = 0.f, s3 = 0.f;
            #pragma unroll
            for (int q = 0; q < 16; ++q) {
                float4 a = mr[q], b = vv[q];
                s0 = fmaf(a.x, b.x, s0); s1 = fmaf(a.y, b.y, s1);
                s2 = fmaf(a.z, b.z, s2); s3 = fmaf(a.w, b.w, s3);
            }
            u[tid] = rcpf((s0 + s1) + (s2 + s3));
        }
        __syncthreads();
        if (tid < 64) {                       // v = 1/(M^T u)
            const float4* mr = reinterpret_cast<const float4*>(&Mt[tid * 68]);
            const float4* uu = reinterpret_cast<const float4*>(u);
            float s0 = 0.f, s1 = 0.f, s2 = 0.f, s3 = 0.f;
            #pragma unroll
            for (int q = 0; q < 16; ++q) {
                float4 a = mr[q], b = uu[q];
                s0 = fmaf(a.x, b.x, s0); s1 = fmaf(a.y, b.y, s1);
                s2 = fmaf(a.z, b.z, s2); s3 = fmaf(a.w, b.w, s3);
            }
            v[tid] = rcpf((s0 + s1) + (s2 + s3));
        }
        __syncthreads();
    }

    // m16n8k16 B-fragment order (R9-verified):
    //   g_Pf[(kt*8+nt)*32 + lane] = { f16x2(P[16kt+2tg][8nt+g], P[16kt+2tg+1][8nt+g]),
    //                                 f16x2(P[16kt+2tg+8][8nt+g], P[16kt+2tg+9][8nt+g]) }
    for (int i = tid; i < 1024; i += 256) {
        int lane = i & 31, ntk = i >> 5;
        int nt = ntk & 7, kt = ntk >> 3;
        int g = lane >> 2, tg = lane & 3;
        int k0 = kt * 16 + 2 * tg, n = nt * 8 + g;
        float p0 = u[k0]     * M[k0 * 68 + n]       * v[n];
        float p1 = u[k0 + 1] * M[(k0 + 1) * 68 + n] * v[n];
        float p8 = u[k0 + 8] * M[(k0 + 8) * 68 + n] * v[n];
        float p9 = u[k0 + 9] * M[(k0 + 9) * 68 + n] * v[n];
        g_Pf[i] = make_uint2(f16x2_rn(p0, p1), f16x2_rn(p8, p9));
    }

    // Per-layer constants: r = A + bw0*xc + bw1*yc + C * exp2(e0*log2(xs)+e1*log2(ys))
    if (tid < NLAYER) {
        float w0 = weights[tid], w1 = 1.0f - w0, a = biases[tid];
        float A, C, cl, e0 = 0.0f, e1 = 0.0f, off;
        if (fabsf(a - 0.5f) < EPSF) {
            A = 0.0f; cl = 1.0f; C = 0.0f; off = 0.0f;
        } else if (a < 0.5f) {
            float ar = fminf(fmaxf(1.0f - a, -1.0f + EPSF), 2.0f - EPSF);
            float p  = sqrtf(3.0f / fmaxf(2.0f - ar, EPSF)) - 1.0f;
            e0 = 2.0f * w0 * p; e1 = 2.0f * w1 * p;
            float bl, bg;
            if      (fabsf(ar - 2.0f) < EPSF) { bl = 0.0f; bg = 0.0f; }
            else if (ar >= 0.75f)             { bl = 0.0f; bg = 1.0f; }
            else if (ar > 0.5f)               { bl = 3.0f - 4.0f * ar; bg = 4.0f * ar - 2.0f; }
            else                              { bl = 1.0f; bg = 0.0f; }
            A = 1.0f - bl; cl = bl; C = -bg; off = 1.0f;
        } else {
            float p = sqrtf(3.0f / fmaxf(2.0f - a, EPSF)) - 1.0f;
            e0 = 2.0f * w0 * p; e1 = 2.0f * w1 * p;
            float bl, bg;
            if      (fabsf(a - 2.0f) < EPSF) { bl = 0.0f; bg = 0.0f; }
            else if (a >= 0.75f)             { bl = 0.0f; bg = 1.0f; }
            else if (a > 0.5f)               { bl = 3.0f - 4.0f * a; bg = 4.0f * a - 2.0f; }
            else                             { bl = 1.0f; bg = 0.0f; }
            A = 0.0f; cl = bl; C = bg; off = 0.0f;
        }
        float* lc = &g_lc[tid * 8];
        lc[0] = cl * w0; lc[1] = cl * w1; lc[2] = A;   lc[3] = C;
        lc[4] = e0;      lc[5] = e1;      lc[6] = off; lc[7] = a;
    }
}

// ---------------------------------------------------------------------------
// Main: PERSISTENT warps + cp.async double buffering (R10 structure), with
// layer constants in the constant bank (zero LSU traffic in the scan).
// 444 CTAs x 128 thr; warp-private 2x9216B buffers; grid-stride over 32-row
// tiles. fp16 m16n8k16 MMA, f32 SMEM X (stride-72, A-frag pair = 4g+tg inj),
// SL (64 x 34 f32) aliases the consumed buffer.
// ---------------------------------------------------------------------------
#define XW 72
#define XBUF_W 2304                       // 32*72 words = 9216 B
#define LS 34
#define WSLICE_W (2 * XBUF_W)             // per-warp words
#define SM_SIZE (4 * 2 * 9216)            // 73728 B per CTA -> 3 CTAs/SM
#define NCTAS 444

__global__ __launch_bounds__(128, 3) void main_kernel(const float* __restrict__ x,
                                                      float* __restrict__ out,
                                                      int batch)
{
    extern __shared__ __align__(16) uint8_t smem[];
    const int tid = threadIdx.x, w = tid >> 5, lane = tid & 31;
    const int g = lane >> 2, tg = lane & 3;

    float* Wbase = reinterpret_cast<float*>(smem) + w * WSLICE_W;
    uint32_t sbase;
    asm("{ .reg .u64 t; cvta.to.shared.u64 t, %1; cvt.u32.u64 %0, t; }"
        : "=r"(sbase) : "l"(Wbase));

    const int ntiles = (batch + 31) >> 5;
    const int warpId = blockIdx.x * 4 + w;
    const int wstride = gridDim.x * 4;
    const size_t f4_limit = (size_t)batch * 16;
    const float4* gx = reinterpret_cast<const float4*>(x);

    // issue one 32-row tile into buffer p (16 x 16B cp.async per thread)
    auto issue = [&](int tile, int p) {
        if (tile < ntiles) {
            uint32_t dstb = sbase + p * 9216;
            #pragma unroll
            for (int t = 0; t < 16; ++t) {
                int i = lane + t * 32;
                size_t gi = (size_t)tile * 512 + i;
                if (gi < f4_limit) {
                    int r = i >> 4, c4 = i & 15;
                    uint32_t d = dstb + (uint32_t)(r * XW + c4 * 4) * 4;
                    asm volatile("cp.async.cg.shared.global [%0], [%1], 16;"
                                 :: "r"(d), "l"(gx + gi) : "memory");
                }
            }
        }
        asm volatile("cp.async.commit_group;" ::: "memory");
    };

    issue(warpId, 0);
    issue(warpId + wstride, 1);

    int p = 0;
    for (int tile = warpId; tile < ntiles; tile += wstride) {
        asm volatile("cp.async.wait_group 1;" ::: "memory");
        __syncwarp();

        const float* Xb = Wbase + p * XBUF_W;

        // ---- GEMM: 32 rows x 64 leaves, fp16 m16n8k16, 4 k-steps ----
        float d[2][8][4];
        #pragma unroll
        for (int mt = 0; mt < 2; ++mt)
            #pragma unroll
            for (int nt = 0; nt < 8; ++nt)
                #pragma unroll
                for (int e = 0; e < 4; ++e) d[mt][nt][e] = 0.0f;

        #pragma unroll
        for (int kt = 0; kt < 4; ++kt) {
            const int kc = kt * 16 + 2 * tg;
            uint32_t a[2][4];
            #pragma unroll
            for (int mt = 0; mt < 2; ++mt) {
                int r0 = g + mt * 16;
                a[mt][0] = ldpack(&Xb[r0 * XW + kc]);
                a[mt][1] = ldpack(&Xb[(r0 + 8) * XW + kc]);
                a[mt][2] = ldpack(&Xb[r0 * XW + kc + 8]);
                a[mt][3] = ldpack(&Xb[(r0 + 8) * XW + kc + 8]);
            }
            #pragma unroll
            for (int nt = 0; nt < 8; ++nt) {
                uint2 b = __ldg(&g_Pf[(kt * 8 + nt) * 32 + lane]);
                mma_fp16(d[0][nt], a[0], b.x, b.y);
                mma_fp16(d[1][nt], a[1], b.x, b.y);
            }
        }
        __syncwarp();            // done reading Xb; SL may alias it

        // ---- epilogue: D -> SL[leaf][local row] ----
        float* SLb = Wbase + p * XBUF_W;
        #pragma unroll
        for (int mt = 0; mt < 2; ++mt) {
            int r0 = mt * 16 + g;
            #pragma unroll
            for (int nt = 0; nt < 8; ++nt) {
                int c0 = nt * 8 + tg * 2;
                SLb[c0 * LS + r0]           = d[mt][nt][0];
                SLb[(c0 + 1) * LS + r0]     = d[mt][nt][1];
                SLb[c0 * LS + r0 + 8]       = d[mt][nt][2];
                SLb[(c0 + 1) * LS + r0 + 8] = d[mt][nt][3];
            }
        }
        __syncwarp();

        // ---- 63-layer scan: thread scans its local row (= lane) ----
        // Constants come from the constant bank (c_lc): no loads, ptxas folds
        // them into FFMA/FMNMX operands.
        float state = SLb[lane];
        #pragma unroll
        for (int i = 0; i < NLAYER; ++i) {
            float leaf = SLb[(i + 1) * LS + lane];
            float4 k0 = c_lc[i * 2];
            float4 k1 = c_lc[i * 2 + 1];

            float xc = fminf(fmaxf(state, EPSF), 1.0f - EPSF);
            float yc = fminf(fmaxf(leaf,  EPSF), 1.0f - EPSF);
            float lgx = lg2(fabsf(k1.z - xc));
            float lgy = lg2(fabsf(k1.z - yc));
            float t  = fmaf(k1.x, lgx, k1.y * lgy);
            float gg = ex2(t);
            state = fmaf(k0.w, gg, fmaf(k0.y, yc, fmaf(k0.x, xc, k0.z)));
        }

        int row = tile * 32 + lane;
        if (row < batch) out[row] = state;

        __syncwarp();            // all lanes done reading SLb before refill
        issue(tile + 2 * wstride, p);
        p ^= 1;
    }
}

// ---------------------------------------------------------------------------
// Launch
// ---------------------------------------------------------------------------
extern "C" void kernel_launch(void* const* d_in, const int* in_sizes, int n_in,
                              void* d_out, int out_size)
{
    const float* x       = (const float*)d_in[0];
    const float* logits  = (const float*)d_in[1];
    const float* weights = (const float*)d_in[2];
    const float* biases  = (const float*)d_in[3];
    float* out = (float*)d_out;

    int batch = in_sizes[0] / NINPUT;

    cudaFuncSetAttribute(main_kernel, cudaFuncAttributeMaxDynamicSharedMemorySize, SM_SIZE);

    setup_kernel<<<1, 256>>>(logits, weights, biases);

    // layer consts -> constant bank (D2D async copy; graph-capturable, R6-proven)
    void* lc_dev = nullptr;
    cudaGetSymbolAddress(&lc_dev, g_lc);
    cudaMemcpyToSymbolAsync(c_lc, lc_dev, NLAYER * 8 * sizeof(float), 0,
                            cudaMemcpyDeviceToDevice, 0);

    main_kernel<<<NCTAS, 128, SM_SIZE>>>(x, out, batch);
}